// round 15
// baseline (speedup 1.0000x reference)
#include <cuda_runtime.h>
#include <cuda_bf16.h>
#include <cstdint>

#define B  4
#define N  65536
#define M  128
#define K_POS 128
#define K_NEG 384
#define NSAMP 512

// Output layout (float32, tuple flattened in order)
#define OFF_ROIS 0
#define OFF_LAB  (B*NSAMP*8)              // 16384
#define OFF_VAL  (OFF_LAB + B*NSAMP)      // 18432
#define OFF_ASG  (OFF_VAL + B*NSAMP)      // 20480
#define OFF_MAX  (OFF_ASG + B*N)          // 282624

#define HI_CAP   (1<<18)
#define CAND_CAP 2048
#define NBIN     2048
#define FBLK_X   32
#define FBLOCKS  (FBLK_X * B)             // 128 blocks <= 148 SMs -> one wave

// Scratch: zero-initialized at load; every consumer resets what it reads so
// graph replays see identical initial state.
__device__ int      g_assigned[B * N];
__device__ unsigned g_lqv[B * N];            // M - m of first matching gt; 0 = none
__device__ uint2    g_hi[B][HI_CAP];         // (n | m<<16, iou_bits) for iou>=0.5
__device__ int      g_hicnt[B];
__device__ unsigned g_gtmax[B * M];          // col max bits over pushed pairs
__device__ unsigned g_hist[8 * NBIN];
__device__ unsigned g_barA[B], g_barB[B], g_barC[B];   // per-batch barriers
__device__ unsigned g_exit;
__device__ unsigned long long g_cand[8][CAND_CAP];
__device__ int      g_ccnt[8];

__device__ __forceinline__ void st(float* out, long long idx, float v, long long lim) {
    if (idx < lim) out[idx] = v;
}

// Per-batch spin barrier: FBLK_X arrivals. Caller must be a full block.
__device__ __forceinline__ void batch_barrier(unsigned* ctr, int tid) {
    __syncthreads();
    if (tid == 0) {
        __threadfence();
        atomicAdd(ctr, 1u);
        while (atomicAdd(ctr, 0u) < (unsigned)FBLK_X) __nanosleep(64);
        __threadfence();
    }
    __syncthreads();
}

// Exact IoU matching the JAX op sequence (validated rel_err==0).
__device__ __forceinline__ float iou_exact(float4 bb, float ab, float4 g, float ag) {
    float ltx = fmaxf(bb.x, g.x);
    float lty = fmaxf(bb.y, g.y);
    float rbx = fminf(bb.z, g.z);
    float rby = fminf(bb.w, g.w);
    float w = fmaxf(__fsub_rn(rbx, ltx), 0.0f);
    float h = fmaxf(__fsub_rn(rby, lty), 0.0f);
    float inter = __fmul_rn(w, h);
    float u = __fadd_rn(ab, ag);
    u = __fsub_rn(u, inter);
    u = __fadd_rn(u, 1e-6f);
    return __fdiv_rn(inter, u);
}

// Intersection only, exact reference rounding.
__device__ __forceinline__ float inter_f(float4 bb, float4 g) {
    float ltx = fmaxf(bb.x, g.x);
    float lty = fmaxf(bb.y, g.y);
    float rbx = fminf(bb.z, g.z);
    float rby = fminf(bb.w, g.w);
    float w = fmaxf(__fsub_rn(rbx, ltx), 0.0f);
    float h = fmaxf(__fsub_rn(rby, lty), 0.0f);
    return __fmul_rn(w, h);
}

// Piecewise-monotone bin. Masked values live in [0,1) u [10,11).
// [0,1)  -> bins [0, 1000)   (v*1000, clamped below 1000)
// [10,11)-> bins [1000, 2000) ((v-10) is Sterbenz-exact; *1000 monotone)
__device__ __forceinline__ int val_bin(float v) {
    int iv;
    if (v >= 10.0f) {
        iv = 1000 + (int)(__fmul_rn(__fsub_rn(v, 10.0f), 1000.0f));
    } else {
        iv = (int)(__fmul_rn(v, 1000.0f));
        if (iv > 999) iv = 999;
    }
    if (iv < 0) iv = 0;
    if (iv > NBIN - 1) iv = NBIN - 1;
    return iv;
}

// ---------------------------------------------------------------------------
// Assignment kernel (measured best, unchanged): s-surrogate, FFMA-folded
// cross-mult compare with 2e-6 x-relative margin -> exact rerun; in-loop
// ballot-aggregated pushes maintain g_hi and g_gtmax.
__global__ void __launch_bounds__(128)
assign_fused_kernel(const float4* __restrict__ bboxes,
                    const float4* __restrict__ gts,
                    float* __restrict__ out, long long lim) {
    __shared__ float4 sgt[M];
    __shared__ float  sga[M];
    int b = blockIdx.y;
    int tid = threadIdx.x;
    {
        float4 g = gts[b * M + tid];
        sgt[tid] = g;
        sga[tid] = __fmul_rn(__fsub_rn(g.z, g.x), __fsub_rn(g.w, g.y));
    }
    __syncthreads();
    int n = blockIdx.x * 128 + tid;
    float4 bb = bboxes[(long long)b * N + n];
    float ab = __fmul_rn(__fsub_rn(bb.z, bb.x), __fsub_rn(bb.w, bb.y));
    float ib = 0.0f, sb = 1.0f;              // running best (inter, s) pair
    int bm = 0;
    bool amb = false;
    int lane = tid & 31;
    unsigned lml = (1u << lane) - 1u;

#pragma unroll 4
    for (int m = 0; m < M; m++) {
        float4 g = sgt[m];
        float s = __fadd_rn(ab, sga[m]);     // rn(ab+ag), independent of i
        float i = inter_f(bb, g);
        float x = __fmul_rn(i, sb);
        float nd = __fmaf_rn(ib, s, -x);     // ib*s - x, single rounding
        amb |= (fabsf(nd) < __fmul_rn(x, 2e-6f));
        if (nd < 0.0f) { ib = i; sb = s; bm = m; }
        // conservative superset of {rn(i/u_ref) >= 0.5}: 3.00001*i >= s
        bool p = (__fmul_rn(i, 3.00001f) >= s);
        if (__any_sync(0xffffffffu, p)) {
            float q = 0.0f;
            if (p) {
                float u = __fadd_rn(__fsub_rn(s, i), 1e-6f);   // exact u_ref
                q = __fdiv_rn(i, u);
            }
            bool w = p && (q >= 0.5f);
            unsigned mk = __ballot_sync(0xffffffffu, w);
            int tot = __popc(mk);
            int base = 0;
            if (lane == 0 && tot) base = atomicAdd(&g_hicnt[b], tot);
            base = __shfl_sync(0xffffffffu, base, 0);
            if (w) {
                unsigned qb = __float_as_uint(q);
                atomicMax(&g_gtmax[b * M + m], qb);
                int p2 = base + __popc(mk & lml);
                if (p2 < HI_CAP)
                    g_hi[b][p2] = make_uint2((unsigned)n | ((unsigned)m << 16), qb);
            }
        }
    }
    float q;
    if (amb) {                               // rare: exact rerun in m-order
        float bq = -1.0f; int bmm = 0;
        for (int m = 0; m < M; m++) {
            float qq = iou_exact(bb, ab, sgt[m], sga[m]);
            if (qq > bq) { bq = qq; bmm = m; }
        }
        q = bq; bm = bmm;
    } else {
        // exact reference quotient of the winner: sb == rn(ab+ag_winner)
        float u = __fadd_rn(__fsub_rn(sb, ib), 1e-6f);
        q = __fdiv_rn(ib, u);
    }
    long long o = (long long)b * N + n;
    g_assigned[o] = (q >= 0.5f) ? (bm + 1) : 0;
    st(out, OFF_MAX + o, q, lim);
}

// ---------------------------------------------------------------------------
// Cooperative fused tail: LQ filter -> barA -> finalize + hist -> barB ->
// threshold bins -> register compact -> barC -> in-kernel sort + emit.
// Per-batch barriers (32 blocks each); batches proceed independently.
__global__ void __launch_bounds__(512)
finalize_fused_kernel(const float* __restrict__ prio,
                      const float4* __restrict__ bboxes,
                      const float4* __restrict__ gts,
                      const int* __restrict__ labels,
                      float* __restrict__ out, long long lim) {
    __shared__ unsigned hp[NBIN];
    __shared__ unsigned hn[NBIN];
    __shared__ unsigned long long skeys[CAND_CAP];
    __shared__ int s_btp, s_btn;
    int b = blockIdx.y;
    int tid = threadIdx.x;

#pragma unroll
    for (int j = 0; j < NBIN / 512; j++) {
        hp[tid + j * 512] = 0u;
        hn[tid + j * 512] = 0u;
    }
    if (tid == 0) { s_btp = 0; s_btn = 0; }

    // ---- phase 0: parallel LQ filter (all 32 blocks slice the candidates)
    {
        int c = g_hicnt[b];
        if (c > HI_CAP) c = HI_CAP;
        for (int i = blockIdx.x * 512 + tid; i < c; i += FBLK_X * 512) {
            uint2 e = g_hi[b][i];
            unsigned m = e.x >> 16;
            if (e.y == g_gtmax[b * M + m])
                atomicMax(&g_lqv[(long long)b * N + (e.x & 0xFFFFu)],
                          (unsigned)(M - (int)m));
        }
    }
    // ---- barrier A (per-batch): all g_lqv writes visible
    batch_barrier(&g_barA[b], tid);
    // resets (reads of gtmax/hicnt all happened before barrier A)
    if (blockIdx.x == 2) {
        if (tid < M) g_gtmax[b * M + tid] = 0u;
        if (tid == 0) g_hicnt[b] = 0;
    }

    // ---- phase 1: finalize assigned + histograms (keep a, v in registers)
    const float* pr = prio + (long long)b * N;
    int   av[4];
    float vv[4];
#pragma unroll
    for (int j = 0; j < 4; j++) {
        int n = blockIdx.x * 2048 + j * 512 + tid;
        long long o = (long long)b * N + n;
        int a = g_assigned[o];
        unsigned lv = g_lqv[o];
        if (lv) { a = (M - (int)lv) + 1; g_lqv[o] = 0u; }   // apply + reset
        g_assigned[o] = a;
        st(out, OFF_ASG + o, (float)a, lim);
        float v = pr[n];
        av[j] = a; vv[j] = v;
        float vp = (a > 0)  ? __fadd_rn(v, 10.0f) : v;
        float vn = (a == 0) ? __fadd_rn(v, 10.0f) : v;
        atomicAdd(&hp[val_bin(vp)], 1u);
        atomicAdd(&hn[val_bin(vn)], 1u);
    }
    __syncthreads();
#pragma unroll
    for (int j = 0; j < NBIN / 512; j++) {
        int k = tid + j * 512;
        unsigned xp = hp[k], xn = hn[k];
        if (xp) atomicAdd(&g_hist[(2 * b) * NBIN + k], xp);
        if (xn) atomicAdd(&g_hist[(2 * b + 1) * NBIN + k], xn);
    }
    // ---- barrier B (per-batch): histograms complete
    batch_barrier(&g_barB[b], tid);

    // ---- threshold bins for this batch's two tasks (warp 0: pos, warp 1: neg)
    int w = tid >> 5, lane = tid & 31;
    if (w < 2) {
        int task = 2 * b + w;
        unsigned K = (task & 1) ? K_NEG : K_POS;
        const unsigned* h = &g_hist[task * NBIN];
        unsigned cs = 0;
        for (int j = 0; j < 64; j++) cs += h[lane * 64 + j];
        unsigned acc = cs;
        for (int off = 1; off < 32; off <<= 1) {
            unsigned v = __shfl_down_sync(0xffffffffu, acc, off);
            if (lane + off < 32) acc += v;
        }
        unsigned cum = acc - cs;            // bins in lanes > this one
        for (int d = lane * 64 + 63; d >= lane * 64; --d) {
            unsigned nc = cum + h[d];
            if (nc >= K && cum < K) { if (w == 0) s_btp = d; else s_btn = d; }
            cum = nc;
        }
    }
    __syncthreads();
    int btp = s_btp, btn = s_btn;

    // ---- phase 2: compact from registers
#pragma unroll
    for (int j = 0; j < 4; j++) {
        int n = blockIdx.x * 2048 + j * 512 + tid;
        int a = av[j];
        float v = vv[j];
        float vp = (a > 0)  ? __fadd_rn(v, 10.0f) : v;
        float vn = (a == 0) ? __fadd_rn(v, 10.0f) : v;
        if (val_bin(vp) >= btp) {
            int p = atomicAdd(&g_ccnt[2 * b], 1);
            if (p < CAND_CAP)
                g_cand[2 * b][p] =
                    ((unsigned long long)__float_as_uint(vp) << 32)
                  | (unsigned long long)(0xFFFFFFFFu - (unsigned)n);
        }
        if (val_bin(vn) >= btn) {
            int p = atomicAdd(&g_ccnt[2 * b + 1], 1);
            if (p < CAND_CAP)
                g_cand[2 * b + 1][p] =
                    ((unsigned long long)__float_as_uint(vn) << 32)
                  | (unsigned long long)(0xFFFFFFFFu - (unsigned)n);
        }
    }
    // ---- barrier C (per-batch): candidate lists complete
    batch_barrier(&g_barC[b], tid);

    // ---- phase 3: blocks 0/1 of each batch sort + emit their task
    if (blockIdx.x < 2) {
        int which = blockIdx.x;
        int task = 2 * b + which;
        int K = which ? K_NEG : K_POS;
        int nc = g_ccnt[task];
        if (nc > CAND_CAP) nc = CAND_CAP;
        int P = 512;
        while (P < nc) P <<= 1;
        for (int i = tid; i < P; i += 512)
            skeys[i] = (i < nc) ? g_cand[task][i] : 0ULL;
        __syncthreads();
        for (int kk = 2; kk <= P; kk <<= 1) {
            for (int j = kk >> 1; j > 0; j >>= 1) {
                for (int i = tid; i < P; i += 512) {
                    int l = i ^ j;
                    if (l > i) {
                        unsigned long long a = skeys[i], c = skeys[l];
                        bool desc = ((i & kk) == 0);
                        if (desc ? (a < c) : (a > c)) { skeys[i] = c; skeys[l] = a; }
                    }
                }
                __syncthreads();
            }
        }
        for (int i = tid; i < K; i += 512) {
            unsigned idx = 0xFFFFFFFFu - (unsigned)(skeys[i] & 0xFFFFFFFFull);
            float4 bb = bboxes[(long long)b * N + idx];
            int a = g_assigned[(long long)b * N + idx];
            float4 tgt = make_float4(0.f, 0.f, 0.f, 0.f);
            float lab, val;
            int row;
            if (!which) {
                row = i;
                bool v = (a > 0);
                int gi = a - 1; if (gi < 0) gi = 0;
                if (v) {
                    tgt = gts[b * M + gi];
                    lab = (float)labels[b * M + gi];
                } else {
                    lab = -1.0f;
                }
                val = v ? 1.0f : 0.0f;
            } else {
                row = K_POS + i;
                lab = 0.0f;
                val = (a == 0) ? 1.0f : 0.0f;
            }
            long long r = (long long)(b * NSAMP + row);
            long long ro = OFF_ROIS + r * 8;
            st(out, ro + 0, bb.x, lim); st(out, ro + 1, bb.y, lim);
            st(out, ro + 2, bb.z, lim); st(out, ro + 3, bb.w, lim);
            st(out, ro + 4, tgt.x, lim); st(out, ro + 5, tgt.y, lim);
            st(out, ro + 6, tgt.z, lim); st(out, ro + 7, tgt.w, lim);
            st(out, OFF_LAB + r, lab, lim);
            st(out, OFF_VAL + r, val, lim);
        }
        __syncthreads();
        // resets for next replay (everyone is past the hist/cand reads)
        for (int i = tid; i < NBIN; i += 512) g_hist[task * NBIN + i] = 0u;
        if (tid == 0) g_ccnt[task] = 0;
    }

    // ---- exit: last block (grid-wide) resets barrier counters
    if (tid == 0) {
        __threadfence();
        unsigned r = atomicAdd(&g_exit, 1u);
        if (r == (unsigned)(FBLOCKS - 1)) {
            for (int i = 0; i < B; i++) {
                g_barA[i] = 0u; g_barB[i] = 0u; g_barC[i] = 0u;
            }
            __threadfence();
            g_exit = 0u;
        }
    }
}

extern "C" void kernel_launch(void* const* d_in, const int* in_sizes, int n_in,
                              void* d_out, int out_size) {
    const float4* bboxes = (const float4*)d_in[0];   // [B,N,4] f32
    const float4* gts    = (const float4*)d_in[1];   // [B,M,4] f32
    const int*    labels = (const int*)d_in[2];      // [B,M] i32
    const float*  prio   = (const float*)d_in[3];    // [B,N] f32
    float* out = (float*)d_out;
    long long lim = (long long)out_size;

    assign_fused_kernel<<<dim3(N / 128, B), 128>>>(bboxes, gts, out, lim);
    finalize_fused_kernel<<<dim3(FBLK_X, B), 512>>>(prio, bboxes, gts, labels,
                                                    out, lim);
}

// round 16
// speedup vs baseline: 1.0327x; 1.0327x over previous
#include <cuda_runtime.h>
#include <cuda_bf16.h>
#include <cstdint>

#define B  4
#define N  65536
#define M  128
#define K_POS 128
#define K_NEG 384
#define NSAMP 512

// Output layout (float32, tuple flattened in order)
#define OFF_ROIS 0
#define OFF_LAB  (B*NSAMP*8)              // 16384
#define OFF_VAL  (OFF_LAB + B*NSAMP)      // 18432
#define OFF_ASG  (OFF_VAL + B*NSAMP)      // 20480
#define OFF_MAX  (OFF_ASG + B*N)          // 282624

#define HI_CAP   (1<<18)
#define CAND_CAP 2048
#define NBIN     2048
#define FBLK_X   32
#define FBLOCKS  (FBLK_X * B)             // 128 blocks <= 148 SMs -> one wave

// Scratch: zero-initialized at load; every consumer resets what it reads so
// graph replays see identical initial state.
__device__ int      g_assigned[B * N];
__device__ unsigned g_lqv[B * N];            // M - m of first matching gt; 0 = none
__device__ uint2    g_hi[B][HI_CAP];         // (n | m<<16, iou_bits) for iou>=0.5
__device__ int      g_hicnt[B];
__device__ unsigned g_gtmax[B * M];          // col max bits over pushed pairs
__device__ unsigned g_hist[8 * NBIN];
__device__ unsigned g_barA[B], g_barB[B];    // per-batch barriers
__device__ unsigned g_exit;
__device__ unsigned long long g_cand[8][CAND_CAP];
__device__ int      g_ccnt[8];

__device__ __forceinline__ void st(float* out, long long idx, float v, long long lim) {
    if (idx < lim) out[idx] = v;
}

// Per-batch spin barrier: FBLK_X arrivals. Caller must be a full block.
__device__ __forceinline__ void batch_barrier(unsigned* ctr, int tid) {
    __syncthreads();
    if (tid == 0) {
        __threadfence();
        atomicAdd(ctr, 1u);
        while (atomicAdd(ctr, 0u) < (unsigned)FBLK_X) __nanosleep(64);
        __threadfence();
    }
    __syncthreads();
}

// Exact IoU matching the JAX op sequence (validated rel_err==0).
__device__ __forceinline__ float iou_exact(float4 bb, float ab, float4 g, float ag) {
    float ltx = fmaxf(bb.x, g.x);
    float lty = fmaxf(bb.y, g.y);
    float rbx = fminf(bb.z, g.z);
    float rby = fminf(bb.w, g.w);
    float w = fmaxf(__fsub_rn(rbx, ltx), 0.0f);
    float h = fmaxf(__fsub_rn(rby, lty), 0.0f);
    float inter = __fmul_rn(w, h);
    float u = __fadd_rn(ab, ag);
    u = __fsub_rn(u, inter);
    u = __fadd_rn(u, 1e-6f);
    return __fdiv_rn(inter, u);
}

// Intersection only, exact reference rounding.
__device__ __forceinline__ float inter_f(float4 bb, float4 g) {
    float ltx = fmaxf(bb.x, g.x);
    float lty = fmaxf(bb.y, g.y);
    float rbx = fminf(bb.z, g.z);
    float rby = fminf(bb.w, g.w);
    float w = fmaxf(__fsub_rn(rbx, ltx), 0.0f);
    float h = fmaxf(__fsub_rn(rby, lty), 0.0f);
    return __fmul_rn(w, h);
}

// Piecewise-monotone bin. Masked values live in [0,1) u [10,11).
__device__ __forceinline__ int val_bin(float v) {
    int iv;
    if (v >= 10.0f) {
        iv = 1000 + (int)(__fmul_rn(__fsub_rn(v, 10.0f), 1000.0f));
    } else {
        iv = (int)(__fmul_rn(v, 1000.0f));
        if (iv > 999) iv = 999;
    }
    if (iv < 0) iv = 0;
    if (iv > NBIN - 1) iv = NBIN - 1;
    return iv;
}

// ---------------------------------------------------------------------------
// Assignment kernel (measured best, unchanged): s-surrogate, FFMA-folded
// cross-mult compare with 2e-6 x-relative margin -> exact rerun; in-loop
// ballot-aggregated pushes maintain g_hi and g_gtmax.
__global__ void __launch_bounds__(128)
assign_fused_kernel(const float4* __restrict__ bboxes,
                    const float4* __restrict__ gts,
                    float* __restrict__ out, long long lim) {
    __shared__ float4 sgt[M];
    __shared__ float  sga[M];
    int b = blockIdx.y;
    int tid = threadIdx.x;
    {
        float4 g = gts[b * M + tid];
        sgt[tid] = g;
        sga[tid] = __fmul_rn(__fsub_rn(g.z, g.x), __fsub_rn(g.w, g.y));
    }
    __syncthreads();
    int n = blockIdx.x * 128 + tid;
    float4 bb = bboxes[(long long)b * N + n];
    float ab = __fmul_rn(__fsub_rn(bb.z, bb.x), __fsub_rn(bb.w, bb.y));
    float ib = 0.0f, sb = 1.0f;              // running best (inter, s) pair
    int bm = 0;
    bool amb = false;
    int lane = tid & 31;
    unsigned lml = (1u << lane) - 1u;

#pragma unroll 4
    for (int m = 0; m < M; m++) {
        float4 g = sgt[m];
        float s = __fadd_rn(ab, sga[m]);     // rn(ab+ag), independent of i
        float i = inter_f(bb, g);
        float x = __fmul_rn(i, sb);
        float nd = __fmaf_rn(ib, s, -x);     // ib*s - x, single rounding
        amb |= (fabsf(nd) < __fmul_rn(x, 2e-6f));
        if (nd < 0.0f) { ib = i; sb = s; bm = m; }
        // conservative superset of {rn(i/u_ref) >= 0.5}: 3.00001*i >= s
        bool p = (__fmul_rn(i, 3.00001f) >= s);
        if (__any_sync(0xffffffffu, p)) {
            float q = 0.0f;
            if (p) {
                float u = __fadd_rn(__fsub_rn(s, i), 1e-6f);   // exact u_ref
                q = __fdiv_rn(i, u);
            }
            bool w = p && (q >= 0.5f);
            unsigned mk = __ballot_sync(0xffffffffu, w);
            int tot = __popc(mk);
            int base = 0;
            if (lane == 0 && tot) base = atomicAdd(&g_hicnt[b], tot);
            base = __shfl_sync(0xffffffffu, base, 0);
            if (w) {
                unsigned qb = __float_as_uint(q);
                atomicMax(&g_gtmax[b * M + m], qb);
                int p2 = base + __popc(mk & lml);
                if (p2 < HI_CAP)
                    g_hi[b][p2] = make_uint2((unsigned)n | ((unsigned)m << 16), qb);
            }
        }
    }
    float q;
    if (amb) {                               // rare: exact rerun in m-order
        float bq = -1.0f; int bmm = 0;
        for (int m = 0; m < M; m++) {
            float qq = iou_exact(bb, ab, sgt[m], sga[m]);
            if (qq > bq) { bq = qq; bmm = m; }
        }
        q = bq; bm = bmm;
    } else {
        // exact reference quotient of the winner: sb == rn(ab+ag_winner)
        float u = __fadd_rn(__fsub_rn(sb, ib), 1e-6f);
        q = __fdiv_rn(ib, u);
    }
    long long o = (long long)b * N + n;
    g_assigned[o] = (q >= 0.5f) ? (bm + 1) : 0;
    st(out, OFF_MAX + o, q, lim);
}

// ---------------------------------------------------------------------------
// Cooperative fused tail, restructured around the mask-invariance fact
// (LQ never changes positivity when pos_thr == neg_thr == 0.5):
//   phase A: hist from PRELIM assigned (a, v kept in regs) + LQ filter
//   bar1   : hist + lqv complete
//   phase B: bt + register compact (prelim masks == final masks) +
//            apply lqv -> final assigned -> write ASG -> reset lqv
//   bar2   : candidates + final assigned complete
//   phase C: blocks 0/1 sort + emit; resets.
__global__ void __launch_bounds__(512)
finalize_fused_kernel(const float* __restrict__ prio,
                      const float4* __restrict__ bboxes,
                      const float4* __restrict__ gts,
                      const int* __restrict__ labels,
                      float* __restrict__ out, long long lim) {
    __shared__ unsigned hp[NBIN];
    __shared__ unsigned hn[NBIN];
    __shared__ unsigned long long skeys[CAND_CAP];
    __shared__ int s_btp, s_btn;
    int b = blockIdx.y;
    int tid = threadIdx.x;

#pragma unroll
    for (int j = 0; j < NBIN / 512; j++) {
        hp[tid + j * 512] = 0u;
        hn[tid + j * 512] = 0u;
    }
    if (tid == 0) { s_btp = 0; s_btn = 0; }
    __syncthreads();

    // ---- phase A1: histograms from prelim assigned (keep a, v in registers)
    const float* pr = prio + (long long)b * N;
    int   av[4];
    float vv[4];
#pragma unroll
    for (int j = 0; j < 4; j++) {
        int n = blockIdx.x * 2048 + j * 512 + tid;
        long long o = (long long)b * N + n;
        int a = g_assigned[o];               // prelim; positivity == final
        float v = pr[n];
        av[j] = a; vv[j] = v;
        float vp = (a > 0)  ? __fadd_rn(v, 10.0f) : v;
        float vn = (a == 0) ? __fadd_rn(v, 10.0f) : v;
        atomicAdd(&hp[val_bin(vp)], 1u);
        atomicAdd(&hn[val_bin(vn)], 1u);
    }
    __syncthreads();
#pragma unroll
    for (int j = 0; j < NBIN / 512; j++) {
        int k = tid + j * 512;
        unsigned xp = hp[k], xn = hn[k];
        if (xp) atomicAdd(&g_hist[(2 * b) * NBIN + k], xp);
        if (xn) atomicAdd(&g_hist[(2 * b + 1) * NBIN + k], xn);
    }

    // ---- phase A2: LQ filter (independent of A1; no barrier between)
    {
        int c = g_hicnt[b];
        if (c > HI_CAP) c = HI_CAP;
        for (int i = blockIdx.x * 512 + tid; i < c; i += FBLK_X * 512) {
            uint2 e = g_hi[b][i];
            unsigned m = e.x >> 16;
            if (e.y == g_gtmax[b * M + m])
                atomicMax(&g_lqv[(long long)b * N + (e.x & 0xFFFFu)],
                          (unsigned)(M - (int)m));
        }
    }

    // ---- barrier 1 (per-batch): hist merged, lqv complete
    batch_barrier(&g_barA[b], tid);
    // resets (gtmax/hicnt reads all happened before barrier 1)
    if (blockIdx.x == 2) {
        if (tid < M) g_gtmax[b * M + tid] = 0u;
        if (tid == 0) g_hicnt[b] = 0;
    }

    // ---- phase B1: threshold bins (warp 0: pos, warp 1: neg)
    int w = tid >> 5, lane = tid & 31;
    if (w < 2) {
        int task = 2 * b + w;
        unsigned K = (task & 1) ? K_NEG : K_POS;
        const unsigned* h = &g_hist[task * NBIN];
        unsigned cs = 0;
        for (int j = 0; j < 64; j++) cs += h[lane * 64 + j];
        unsigned acc = cs;
        for (int off = 1; off < 32; off <<= 1) {
            unsigned v = __shfl_down_sync(0xffffffffu, acc, off);
            if (lane + off < 32) acc += v;
        }
        unsigned cum = acc - cs;            // bins in lanes > this one
        for (int d = lane * 64 + 63; d >= lane * 64; --d) {
            unsigned nc = cum + h[d];
            if (nc >= K && cum < K) { if (w == 0) s_btp = d; else s_btn = d; }
            cum = nc;
        }
    }
    __syncthreads();
    int btp = s_btp, btn = s_btn;

    // ---- phase B2: compact from registers (prelim masks) + finalize assigned
#pragma unroll
    for (int j = 0; j < 4; j++) {
        int n = blockIdx.x * 2048 + j * 512 + tid;
        long long o = (long long)b * N + n;
        int a = av[j];
        float v = vv[j];
        float vp = (a > 0)  ? __fadd_rn(v, 10.0f) : v;
        float vn = (a == 0) ? __fadd_rn(v, 10.0f) : v;
        if (val_bin(vp) >= btp) {
            int p = atomicAdd(&g_ccnt[2 * b], 1);
            if (p < CAND_CAP)
                g_cand[2 * b][p] =
                    ((unsigned long long)__float_as_uint(vp) << 32)
                  | (unsigned long long)(0xFFFFFFFFu - (unsigned)n);
        }
        if (val_bin(vn) >= btn) {
            int p = atomicAdd(&g_ccnt[2 * b + 1], 1);
            if (p < CAND_CAP)
                g_cand[2 * b + 1][p] =
                    ((unsigned long long)__float_as_uint(vn) << 32)
                  | (unsigned long long)(0xFFFFFFFFu - (unsigned)n);
        }
        // apply LQ correction -> final assigned; write ASG output; reset lqv
        unsigned lv = g_lqv[o];
        if (lv) { a = (M - (int)lv) + 1; g_lqv[o] = 0u; }
        g_assigned[o] = a;
        st(out, OFF_ASG + o, (float)a, lim);
    }

    // ---- barrier 2 (per-batch): candidates + final assigned complete
    batch_barrier(&g_barB[b], tid);

    // ---- phase C: blocks 0/1 of each batch sort + emit their task
    if (blockIdx.x < 2) {
        int which = blockIdx.x;
        int task = 2 * b + which;
        int K = which ? K_NEG : K_POS;
        int nc = g_ccnt[task];
        if (nc > CAND_CAP) nc = CAND_CAP;
        int P = 512;
        while (P < nc) P <<= 1;
        for (int i = tid; i < P; i += 512)
            skeys[i] = (i < nc) ? g_cand[task][i] : 0ULL;
        __syncthreads();
        for (int kk = 2; kk <= P; kk <<= 1) {
            for (int j = kk >> 1; j > 0; j >>= 1) {
                for (int i = tid; i < P; i += 512) {
                    int l = i ^ j;
                    if (l > i) {
                        unsigned long long a = skeys[i], c = skeys[l];
                        bool desc = ((i & kk) == 0);
                        if (desc ? (a < c) : (a > c)) { skeys[i] = c; skeys[l] = a; }
                    }
                }
                __syncthreads();
            }
        }
        for (int i = tid; i < K; i += 512) {
            unsigned idx = 0xFFFFFFFFu - (unsigned)(skeys[i] & 0xFFFFFFFFull);
            float4 bb = bboxes[(long long)b * N + idx];
            int a = g_assigned[(long long)b * N + idx];   // final (post bar2)
            float4 tgt = make_float4(0.f, 0.f, 0.f, 0.f);
            float lab, val;
            int row;
            if (!which) {
                row = i;
                bool v = (a > 0);
                int gi = a - 1; if (gi < 0) gi = 0;
                if (v) {
                    tgt = gts[b * M + gi];
                    lab = (float)labels[b * M + gi];
                } else {
                    lab = -1.0f;
                }
                val = v ? 1.0f : 0.0f;
            } else {
                row = K_POS + i;
                lab = 0.0f;
                val = (a == 0) ? 1.0f : 0.0f;
            }
            long long r = (long long)(b * NSAMP + row);
            long long ro = OFF_ROIS + r * 8;
            st(out, ro + 0, bb.x, lim); st(out, ro + 1, bb.y, lim);
            st(out, ro + 2, bb.z, lim); st(out, ro + 3, bb.w, lim);
            st(out, ro + 4, tgt.x, lim); st(out, ro + 5, tgt.y, lim);
            st(out, ro + 6, tgt.z, lim); st(out, ro + 7, tgt.w, lim);
            st(out, OFF_LAB + r, lab, lim);
            st(out, OFF_VAL + r, val, lim);
        }
        __syncthreads();
        // resets for next replay (everyone is past the hist/cand reads)
        for (int i = tid; i < NBIN; i += 512) g_hist[task * NBIN + i] = 0u;
        if (tid == 0) g_ccnt[task] = 0;
    }

    // ---- exit: last block (grid-wide) resets barrier counters
    if (tid == 0) {
        __threadfence();
        unsigned r = atomicAdd(&g_exit, 1u);
        if (r == (unsigned)(FBLOCKS - 1)) {
            for (int i = 0; i < B; i++) { g_barA[i] = 0u; g_barB[i] = 0u; }
            __threadfence();
            g_exit = 0u;
        }
    }
}

extern "C" void kernel_launch(void* const* d_in, const int* in_sizes, int n_in,
                              void* d_out, int out_size) {
    const float4* bboxes = (const float4*)d_in[0];   // [B,N,4] f32
    const float4* gts    = (const float4*)d_in[1];   // [B,M,4] f32
    const int*    labels = (const int*)d_in[2];      // [B,M] i32
    const float*  prio   = (const float*)d_in[3];    // [B,N] f32
    float* out = (float*)d_out;
    long long lim = (long long)out_size;

    assign_fused_kernel<<<dim3(N / 128, B), 128>>>(bboxes, gts, out, lim);
    finalize_fused_kernel<<<dim3(FBLK_X, B), 512>>>(prio, bboxes, gts, labels,
                                                    out, lim);
}